// round 15
// baseline (speedup 1.0000x reference)
#include <cuda_runtime.h>
#include <cuda_bf16.h>
#include <math.h>
#include <cstdint>

// InformerLayer: b=4,N=32,T=256 -> B=128 seqs, L=256, C=128, H=8, E=16, DFF=512, u=k=18
#define TOK 32768
#define UK  18

__device__ float g_Aq[128], g_Bq[128], g_Ak[128], g_Bk[128], g_Av[128], g_Bv[128];
__device__ float g_c1[8], g_c2[8], g_c3[8], g_c4[8];
__device__ float g_Po[8 * 128], g_Co[128];
__device__ int   g_idx[256 * UK];
__device__ float g_zm[10];
__device__ float g_G[100];
__device__ float g_V[12 * 128];
__device__ float g_alpha[8 * TOK];           // [h][token], coalesced both sides
__device__ float g_out2[TOK * 128];
__device__ float g_w1c[512 * 128];           // L2-warm copy of w1
__device__ uint2 g_w1f2[64 * 32];            // W1' B-frags: [ntile][lane]
__device__ unsigned g_w2f[16 * 16 * 32 * 4]; // w2 B-frags: [nb][g][lane][4]

static __device__ __forceinline__ unsigned packbf(float a, float b) {
    __nv_bfloat162 t = __floats2bfloat162_rn(a, b);
    return *reinterpret_cast<unsigned *>(&t);
}

__device__ __forceinline__ void mma16816(float &d0, float &d1, float &d2, float &d3,
                                         unsigned a0, unsigned a1, unsigned a2, unsigned a3,
                                         unsigned b0, unsigned b1) {
    asm volatile("mma.sync.aligned.m16n8k16.row.col.f32.bf16.bf16.f32 "
                 "{%0,%1,%2,%3},{%4,%5,%6,%7},{%8,%9},{%0,%1,%2,%3};"
                 : "+f"(d0), "+f"(d1), "+f"(d2), "+f"(d3)
                 : "r"(a0), "r"(a1), "r"(a2), "r"(a3), "r"(b0), "r"(b1));
}

#define LDMX4(r, addr) \
    asm volatile("ldmatrix.sync.aligned.m8n8.x4.shared.b16 {%0,%1,%2,%3}, [%4];" \
                 : "=r"((r)[0]), "=r"((r)[1]), "=r"((r)[2]), "=r"((r)[3]) : "r"(addr))

static __device__ __forceinline__ uint32_t smem_u32(const void *p) {
    uint32_t a;
    asm("{ .reg .u64 t; cvta.to.shared.u64 t, %1; cvt.u32.u64 %0, t; }" : "=r"(a) : "l"(p));
    return a;
}

// monotone int key: unsigned compare == float compare (no NaNs in inputs)
static __device__ __forceinline__ unsigned fkey(float f) {
    int m = __float_as_int(f);
    return (unsigned)m ^ ((unsigned)(m >> 31) | 0x80000000u);
}

// ------------------------------- Threefry ---------------------------------
__device__ __forceinline__ void tf_r(unsigned &x0, unsigned &x1, int r) {
    x0 += x1; x1 = (x1 << r) | (x1 >> (32 - r)); x1 ^= x0;
}
__device__ void threefry2x32(unsigned k0, unsigned k1, unsigned c0, unsigned c1,
                             unsigned &o0, unsigned &o1) {
    unsigned ks2 = k0 ^ k1 ^ 0x1BD11BDAu;
    unsigned x0 = c0 + k0, x1 = c1 + k1;
    tf_r(x0,x1,13); tf_r(x0,x1,15); tf_r(x0,x1,26); tf_r(x0,x1,6);
    x0 += k1;  x1 += ks2 + 1u;
    tf_r(x0,x1,17); tf_r(x0,x1,29); tf_r(x0,x1,16); tf_r(x0,x1,24);
    x0 += ks2; x1 += k0 + 2u;
    tf_r(x0,x1,13); tf_r(x0,x1,15); tf_r(x0,x1,26); tf_r(x0,x1,6);
    x0 += k0;  x1 += k1 + 3u;
    tf_r(x0,x1,17); tf_r(x0,x1,29); tf_r(x0,x1,16); tf_r(x0,x1,24);
    x0 += k1;  x1 += ks2 + 4u;
    tf_r(x0,x1,13); tf_r(x0,x1,15); tf_r(x0,x1,26); tf_r(x0,x1,6);
    x0 += ks2; x1 += k0 + 5u;
    o0 = x0; o1 = x1;
}

// ---- setup_a: Aq..Bv + threefry idx + w2 frags + w1 L2-warm copy ----------
__global__ void __launch_bounds__(256)
setup_a(const float *__restrict__ mlp_w, const float *__restrict__ mlp_b,
        const float *__restrict__ wq, const float *__restrict__ bq,
        const float *__restrict__ wk, const float *__restrict__ bk,
        const float *__restrict__ wv, const float *__restrict__ bv,
        const float *__restrict__ w2, const float *__restrict__ w1) {
    int b = blockIdx.x, tid = threadIdx.x, lane = tid & 31, wid = tid >> 5;
    if (b < 16) {
        int c = b * 8 + wid;
        float aq = 0.f, bq2 = 0.f, ak = 0.f, bk2 = 0.f, av = 0.f, bv2 = 0.f;
#pragma unroll
        for (int m = 0; m < 4; ++m) {
            int j = lane + 32 * m;
            float mw = mlp_w[j], mb = mlp_b[j];
            float q = wq[c * 128 + j], k = wk[c * 128 + j], v = wv[c * 128 + j];
            aq = fmaf(mw, q, aq); bq2 = fmaf(mb, q, bq2);
            ak = fmaf(mw, k, ak); bk2 = fmaf(mb, k, bk2);
            av = fmaf(mw, v, av); bv2 = fmaf(mb, v, bv2);
        }
#pragma unroll
        for (int o = 16; o > 0; o >>= 1) {
            aq  += __shfl_xor_sync(0xffffffffu, aq, o);
            bq2 += __shfl_xor_sync(0xffffffffu, bq2, o);
            ak  += __shfl_xor_sync(0xffffffffu, ak, o);
            bk2 += __shfl_xor_sync(0xffffffffu, bk2, o);
            av  += __shfl_xor_sync(0xffffffffu, av, o);
            bv2 += __shfl_xor_sync(0xffffffffu, bv2, o);
        }
        if (lane == 0) {
            g_Aq[c] = aq; g_Bq[c] = bq2 + bq[c];
            g_Ak[c] = ak; g_Bk[c] = bk2 + bk[c];
            g_Av[c] = av; g_Bv[c] = bv2 + bv[c];
        }
    } else if (b < 25) {
        int i = (b - 16) * 256 + tid;
        unsigned a0, a1, b0, b1;
        threefry2x32(0u, 42u, 0u, 2u, a0, a1);
        threefry2x32(0u, 42u, 1u, 3u, b0, b1);
        unsigned y0, y1;
        threefry2x32(a1, b1, (unsigned)i, (unsigned)(2304 + i), y0, y1);
        g_idx[i]        = (int)(y0 & 255u);
        g_idx[2304 + i] = (int)(y1 & 255u);
    } else if (b < 153) {
        int j2 = (b - 25) * 256 + tid;
        int jj = j2 & 3, u4 = j2 >> 2;
        int ln = u4 & 31, g = (u4 >> 5) & 15, nb = u4 >> 9;
        int n = nb * 8 + (ln >> 2);
        int kp = g * 16 + (ln & 3) + jj * 4;
        g_w2f[j2] = packbf(w2[n * 512 + 2 * kp], w2[n * 512 + 2 * kp + 1]);
    } else {
        int j = (b - 153) * 256 + tid;
        const float4 *src = (const float4 *)w1;
        float4 *dst = (float4 *)g_w1c;
        dst[j] = src[j];
        dst[j + 8192] = src[j + 8192];
    }
}

// ---- setup_b: Co + Po (warp/c) + c1..c4 ------------------------------------
__global__ void __launch_bounds__(256)
setup_b(const float *__restrict__ wo, const float *__restrict__ bo) {
    int b = blockIdx.x, tid = threadIdx.x, lane = tid & 31, wid = tid >> 5;
    if (b < 16) {
        int c = b * 8 + wid;
        float co = 0.f, pv[4];
#pragma unroll
        for (int m = 0; m < 4; ++m) {
            int j = lane + 32 * m;
            float w = wo[c * 128 + j];
            co = fmaf(g_Bv[j], w, co);
            pv[m] = g_Av[j] * w;
        }
#pragma unroll
        for (int o = 16; o > 0; o >>= 1) co += __shfl_xor_sync(0xffffffffu, co, o);
#pragma unroll
        for (int o = 8; o > 0; o >>= 1)
#pragma unroll
            for (int m = 0; m < 4; ++m) pv[m] += __shfl_xor_sync(0xffffffffu, pv[m], o);
        if ((lane & 15) == 0) {
            int hb = lane >> 4;
#pragma unroll
            for (int m = 0; m < 4; ++m) g_Po[(hb + 2 * m) * 128 + c] = pv[m];
        }
        if (lane == 0) g_Co[c] = co + bo[c];
    } else {
        if (tid < 8) {
            int h = tid;
            float c1 = 0.f, c2 = 0.f, c3 = 0.f, c4 = 0.f;
            for (int e = 0; e < 16; ++e) {
                int i = h * 16 + e;
                c1 += g_Aq[i] * g_Ak[i];
                c2 += g_Aq[i] * g_Bk[i];
                c3 += g_Bq[i] * g_Ak[i];
                c4 += g_Bq[i] * g_Bk[i];
            }
            g_c1[h] = c1; g_c2[h] = c2; g_c3[h] = c3; g_c4[h] = c4;
        }
    }
}

// z-basis element
static __device__ __forceinline__ float zb(int i, int c,
                                           const float *mlp_w, const float *mlp_b) {
    if (i == 0) return mlp_w[c];
    if (i <= 8) return g_Po[(i - 1) * 128 + c];
    return mlp_b[c] + g_Co[c];
}

// ---- setup_c: V rows + Gram matrix / means ---------------------------------
__global__ void __launch_bounds__(256)
setup_c(const float *__restrict__ mlp_w, const float *__restrict__ mlp_b,
        const float *__restrict__ ln1g, const float *__restrict__ ln1b) {
    int b = blockIdx.x, tid = threadIdx.x, lane = tid & 31, wid = tid >> 5;
    if (b == 0) {
        if (tid < 128) {
            int c = tid;
            float K = mlp_b[c] + g_Co[c];
            float g = ln1g[c];
            g_V[0 * 128 + c] = mlp_w[c] * g;
#pragma unroll
            for (int h = 0; h < 8; ++h) g_V[(1 + h) * 128 + c] = g_Po[h * 128 + c] * g;
            g_V[9 * 128 + c]  = K * g;
            g_V[10 * 128 + c] = g;
            g_V[11 * 128 + c] = ln1b[c];
        }
    } else {
        int task = (b - 1) * 8 + wid;
        if (task < 100) {
            int i = task / 10, j = task % 10;
            float s = 0.f;
#pragma unroll
            for (int m = 0; m < 4; ++m) {
                int c = lane + 32 * m;
                s = fmaf(zb(i, c, mlp_w, mlp_b), zb(j, c, mlp_w, mlp_b), s);
            }
#pragma unroll
            for (int o = 16; o > 0; o >>= 1) s += __shfl_xor_sync(0xffffffffu, s, o);
            if (lane == 0) g_G[task] = s * (1.0f / 128.0f);
        } else if (task < 110) {
            int i = task - 100;
            float s = 0.f;
#pragma unroll
            for (int m = 0; m < 4; ++m) s += zb(i, lane + 32 * m, mlp_w, mlp_b);
#pragma unroll
            for (int o = 16; o > 0; o >>= 1) s += __shfl_xor_sync(0xffffffffu, s, o);
            if (lane == 0) g_zm[i] = s * (1.0f / 128.0f);
        }
    }
}

// ---- setup_d: W1' = V@w1^T (+b1), warp per n-row ---------------------------
__global__ void __launch_bounds__(256)
setup_d(const float *__restrict__ b1) {
    __shared__ float s[8][12];
    int tid = threadIdx.x, lane = tid & 31, wid = tid >> 5;
    int n = blockIdx.x * 8 + wid;
    float4 wv = *(const float4 *)(g_w1c + n * 128 + lane * 4);
    float p[12];
#pragma unroll
    for (int k = 0; k < 12; ++k) {
        float4 v = *(const float4 *)(g_V + k * 128 + lane * 4);
        p[k] = wv.x * v.x + wv.y * v.y + wv.z * v.z + wv.w * v.w;
    }
#pragma unroll
    for (int o = 16; o > 0; o >>= 1)
#pragma unroll
        for (int k = 0; k < 12; ++k) p[k] += __shfl_xor_sync(0xffffffffu, p[k], o);
    if (lane == 0) {
#pragma unroll
        for (int k = 0; k < 11; ++k) s[wid][k] = p[k];
        s[wid][11] = p[11] + b1[n];
    }
    __syncthreads();
    if (wid == 0) {
        int nr = lane >> 2, q = lane & 3;
        float d0 = s[nr][2 * q], d1 = s[nr][2 * q + 1];
        float d2 = (2 * q + 8 < 12) ? s[nr][2 * q + 8] : 0.f;
        float d3 = (2 * q + 9 < 12) ? s[nr][2 * q + 9] : 0.f;
        g_w1f2[blockIdx.x * 32 + lane] = make_uint2(packbf(d0, d1), packbf(d2, d3));
    }
}

// ------ attention: block = (seq, head); M, redux top-18, softmax -> alpha ---
__global__ void __launch_bounds__(256)
attn_kernel(const float *__restrict__ x) {
    __shared__ float xs[256];
    __shared__ unsigned Ms[256];
    __shared__ int midx[UK];
    int tid = threadIdx.x, lane = tid & 31, wid = tid >> 5;
    int seq = blockIdx.x >> 3, h = blockIdx.x & 7;
    xs[tid] = x[seq * 256 + tid];
    __syncthreads();

    // block stats (every warp computes identical full 256-reduction)
    float s = 0.f, xmax = -3.4e38f, xmin = 3.4e38f;
#pragma unroll
    for (int k = 0; k < 8; ++k) {
        float v = xs[lane + 32 * k];
        s += v; xmax = fmaxf(xmax, v); xmin = fminf(xmin, v);
    }
#pragma unroll
    for (int o = 16; o > 0; o >>= 1) {
        s += __shfl_xor_sync(0xffffffffu, s, o);
        xmax = fmaxf(xmax, __shfl_xor_sync(0xffffffffu, xmax, o));
        xmin = fminf(xmin, __shfl_xor_sync(0xffffffffu, xmin, o));
    }
    float xbar = s * (1.0f / 256.0f);

    float c1 = g_c1[h], c2 = g_c2[h], c3 = g_c3[h], c4 = g_c4[h];

    // per-token: sampled stats + M key (thread = token)
    {
        float pm = -3.4e38f, pn = 3.4e38f, ps = 0.f;
        const int *ip = g_idx + tid * UK;
#pragma unroll
        for (int j = 0; j < UK; ++j) {
            float v = xs[ip[j]];
            pm = fmaxf(pm, v); pn = fminf(pn, v); ps += v;
        }
        float xl = xs[tid];
        float A = fmaf(c1, xl, c3), Bc = fmaf(c2, xl, c4);
        float mx = (A >= 0.f ? A * pm : A * pn) + Bc;
        float sm = fmaf(A, ps, (float)UK * Bc);
        Ms[tid] = fkey(mx - sm * (1.0f / 256.0f));
        g_alpha[(size_t)h * TOK + seq * 256 + tid] = xbar;   // default
    }
    __syncthreads();

    // top-18 (warp 0); ties -> lowest index
    if (wid == 0) {
        unsigned Mkey[8];
#pragma unroll
        for (int k = 0; k < 8; ++k) Mkey[k] = Ms[lane + 32 * k];
        for (int it = 0; it < UK; ++it) {
            unsigned bkey = 0u; int bi = 256;
#pragma unroll
            for (int k = 0; k < 8; ++k) {
                if (Mkey[k] > bkey) { bkey = Mkey[k]; bi = lane + 32 * k; }
            }
            unsigned mkey = __reduce_max_sync(0xffffffffu, bkey);
            unsigned cand = (bkey == mkey) ? (unsigned)bi : 0xFFFFu;
            unsigned mi = __reduce_min_sync(0xffffffffu, cand);
            int m = (int)mi;
#pragma unroll
            for (int k = 0; k < 8; ++k)
                if ((m >> 5) == k && (m & 31) == lane) Mkey[k] = 0u;
            if (lane == 0) midx[it] = m;
        }
    }
    __syncthreads();

    // 18 softmax rows over 8 warps: one paired iteration (rows 0..15) + 2 singles
    {
        int pa = wid, pb = wid + 8;
        int ma = midx[pa], mb = midx[pb];
        float Aa = 0.25f * fmaf(c1, xs[ma], c3);
        float Ab = 0.25f * fmaf(c1, xs[mb], c3);
        float rma = (Aa >= 0.f) ? Aa * xmax : Aa * xmin;
        float rmb = (Ab >= 0.f) ? Ab * xmax : Ab * xmin;
        float Za = 0.f, Sa = 0.f, Zb = 0.f, Sb = 0.f;
#pragma unroll
        for (int k = 0; k < 8; ++k) {
            float xv = xs[lane + 32 * k];
            float ea = __expf(fmaf(Aa, xv, -rma));
            float eb = __expf(fmaf(Ab, xv, -rmb));
            Za += ea; Sa += ea * xv;
            Zb += eb; Sb += eb * xv;
        }
#pragma unroll
        for (int o = 16; o > 0; o >>= 1) {
            Za += __shfl_xor_sync(0xffffffffu, Za, o);
            Sa += __shfl_xor_sync(0xffffffffu, Sa, o);
            Zb += __shfl_xor_sync(0xffffffffu, Zb, o);
            Sb += __shfl_xor_sync(0xffffffffu, Sb, o);
        }
        if (lane == 0) {
            g_alpha[(size_t)h * TOK + seq * 256 + ma] = Sa / Za;
            g_alpha[(size_t)h * TOK + seq * 256 + mb] = Sb / Zb;
        }
    }
    if (wid < 2) {     // rows 16, 17
        int m = midx[16 + wid];
        float A = 0.25f * fmaf(c1, xs[m], c3);
        float rm = (A >= 0.f) ? A * xmax : A * xmin;
        float Z = 0.f, S = 0.f;
#pragma unroll
        for (int k = 0; k < 8; ++k) {
            float xv = xs[lane + 32 * k];
            float e = __expf(fmaf(A, xv, -rm));
            Z += e; S += e * xv;
        }
#pragma unroll
        for (int o = 16; o > 0; o >>= 1) {
            Z += __shfl_xor_sync(0xffffffffu, Z, o);
            S += __shfl_xor_sync(0xffffffffu, S, o);
        }
        if (lane == 0) g_alpha[(size_t)h * TOK + seq * 256 + m] = S / Z;
    }
}

// ---------- FFN + residual + LN2; u computed in prologue from alpha ---------
#define OFF_US (32 * 260)
#define OFF_VS (OFF_US + 32 * 12)
#define OFF_B2 (OFF_VS + 12 * 128)
#define OFF_LG (OFF_B2 + 128)
#define OFF_LB (OFF_LG + 128)
#define OFF_GZ (OFF_LB + 128)
#define FFN_U32 (OFF_GZ + 112)

__global__ void __launch_bounds__(256)
ffn_kernel(const float *__restrict__ x, const float *__restrict__ b2,
           const float *__restrict__ ln2g, const float *__restrict__ ln2b) {
    __shared__ unsigned ts[FFN_U32];
    float *us  = (float *)(ts + OFF_US);
    float *Vs  = (float *)(ts + OFF_VS);
    float *b2s = (float *)(ts + OFF_B2);
    float *lgs = (float *)(ts + OFF_LG);
    float *lbs = (float *)(ts + OFF_LB);
    float *Gz  = (float *)(ts + OFF_GZ);   // [0:100) G, [100:110) zm
    int tid = threadIdx.x;
    int wid = tid >> 5, lane = tid & 31;
    int row0 = blockIdx.x * 32;
    int r = lane >> 2, q = lane & 3;
    int ms = wid >> 2, nq = wid & 3;

    for (int i = tid; i < 12 * 128; i += 256) Vs[i] = g_V[i];
    if (tid < 128) { b2s[tid] = b2[tid]; lgs[tid] = ln2g[tid]; lbs[tid] = ln2b[tid]; }
    if (tid >= 128 && tid < 228) Gz[tid - 128] = g_G[tid - 128];
    if (tid >= 228 && tid < 238) Gz[100 + tid - 228] = g_zm[tid - 228];
    __syncthreads();

    // closed-form LN1 coefficients u for this block's 32 rows
    if (tid < 32) {
        int row = row0 + tid;
        float y[10];
        y[0] = x[row];
#pragma unroll
        for (int hh = 0; hh < 8; ++hh) y[1 + hh] = g_alpha[(size_t)hh * TOK + row];
        y[9] = 1.f;
        float mu = 0.f;
#pragma unroll
        for (int i = 0; i < 10; ++i) mu = fmaf(y[i], Gz[100 + i], mu);
        float q2 = 0.f;
#pragma unroll
        for (int i = 0; i < 10; ++i) {
            float acc = 0.f;
#pragma unroll
            for (int j = 0; j < 10; ++j) acc = fmaf(Gz[i * 10 + j], y[j], acc);
            q2 = fmaf(y[i], acc, q2);
        }
        float rs = rsqrtf(q2 - mu * mu + 1e-5f);
#pragma unroll
        for (int i = 0; i < 9; ++i) us[tid * 12 + i] = y[i] * rs;
        us[tid * 12 + 9]  = rs;
        us[tid * 12 + 10] = -mu * rs;
        us[tid * 12 + 11] = 1.f;
    }
    __syncthreads();

    // GEMM1: U[32,16] @ W1'^T -> relu -> ts bf16 [32][512]
    {
        const float *u0 = us + (ms * 16 + r) * 12;
        const float *u1 = us + (ms * 16 + r + 8) * 12;
        unsigned a0 = packbf(u0[2 * q], u0[2 * q + 1]);
        unsigned a1 = packbf(u1[2 * q], u1[2 * q + 1]);
        unsigned a2 = (q < 2) ? packbf(u0[8 + 2 * q], u0[9 + 2 * q]) : 0u;
        unsigned a3 = (q < 2) ? packbf(u1[8 + 2 * q], u1[9 + 2 * q]) : 0u;
#pragma unroll 4
        for (int t = 0; t < 16; ++t) {
            int nb = nq * 16 + t;
            uint2 B = g_w1f2[nb * 32 + lane];
            float d0 = 0.f, d1 = 0.f, d2 = 0.f, d3 = 0.f;
            mma16816(d0, d1, d2, d3, a0, a1, a2, a3, B.x, B.y);
            d0 = fmaxf(d0, 0.f); d1 = fmaxf(d1, 0.f);
            d2 = fmaxf(d2, 0.f); d3 = fmaxf(d3, 0.f);
            ts[(ms * 16 + r) * 260 + nb * 4 + q]     = packbf(d0, d1);
            ts[(ms * 16 + r + 8) * 260 + nb * 4 + q] = packbf(d2, d3);
        }
    }
    __syncthreads();

    // GEMM2: T[32,512] @ w2^T
    float d[4][4];
#pragma unroll
    for (int t = 0; t < 4; ++t) { d[t][0]=0.f; d[t][1]=0.f; d[t][2]=0.f; d[t][3]=0.f; }
    {
        uint32_t lmbase = smem_u32(ts)
            + (uint32_t)((ms * 16 + ((lane >> 3) & 1) * 8 + (lane & 7)) * 1040)
            + (uint32_t)(((lane >> 4) & 1) * 16);
        const uint4 *W2 = (const uint4 *)g_w2f;
#pragma unroll 2
        for (int g = 0; g < 16; ++g) {
            unsigned a0v[4], a1v[4];
            LDMX4(a0v, lmbase + 64 * g);
            LDMX4(a1v, lmbase + 64 * g + 32);
#pragma unroll
            for (int t = 0; t < 4; ++t) {
                uint4 B = W2[(((nq * 4 + t) * 16) + g) * 32 + lane];
                mma16816(d[t][0], d[t][1], d[t][2], d[t][3],
                         a0v[0], a0v[1], a0v[2], a0v[3], B.x, B.y);
                mma16816(d[t][0], d[t][1], d[t][2], d[t][3],
                         a1v[0], a1v[1], a1v[2], a1v[3], B.z, B.w);
            }
        }
    }
    __syncthreads();

    // ys = y + b2 + residual (x1 = u@V fp32)
    float *ys = (float *)ts;
    {
        int rr = ms * 16 + r;
#pragma unroll
        for (int t = 0; t < 4; ++t) {
            int c0 = nq * 32 + t * 8 + q * 2;
            float x00 = 0.f, x01 = 0.f, x10 = 0.f, x11 = 0.f;
#pragma unroll
            for (int k = 0; k < 12; ++k) {
                float v0 = Vs[k * 128 + c0], v1 = Vs[k * 128 + c0 + 1];
                float uu0 = us[rr * 12 + k], uu1 = us[(rr + 8) * 12 + k];
                x00 = fmaf(uu0, v0, x00); x01 = fmaf(uu0, v1, x01);
                x10 = fmaf(uu1, v0, x10); x11 = fmaf(uu1, v1, x11);
            }
            float bbx = b2s[c0], bby = b2s[c0 + 1];
            ys[rr * 132 + c0]           = d[t][0] + bbx + x00;
            ys[rr * 132 + c0 + 1]       = d[t][1] + bby + x01;
            ys[(rr + 8) * 132 + c0]     = d[t][2] + bbx + x10;
            ys[(rr + 8) * 132 + c0 + 1] = d[t][3] + bby + x11;
        }
    }
    __syncthreads();

    // LN2: 8 warps x 4 rows
#pragma unroll
    for (int jj = 0; jj < 4; ++jj) {
        int rr = wid * 4 + jj;
        float z[4];
#pragma unroll
        for (int j = 0; j < 4; ++j) z[j] = ys[rr * 132 + lane + 32 * j];
        float s2 = z[0] + z[1] + z[2] + z[3];
#pragma unroll
        for (int o = 16; o > 0; o >>= 1) s2 += __shfl_xor_sync(0xffffffffu, s2, o);
        float mu = s2 * (1.0f / 128.0f);
        float v = 0.f;
#pragma unroll
        for (int j = 0; j < 4; ++j) { float dd = z[j] - mu; v += dd * dd; }
#pragma unroll
        for (int o = 16; o > 0; o >>= 1) v += __shfl_xor_sync(0xffffffffu, v, o);
        float rstd = rsqrtf(v * (1.0f / 128.0f) + 1e-5f);
#pragma unroll
        for (int j = 0; j < 4; ++j) {
            int c = lane + 32 * j;
            g_out2[(size_t)(row0 + rr) * 128 + c] = (z[j] - mu) * rstd * lgs[c] + lbs[c];
        }
    }
}

// ----- out[b,c,t] = sum_n out2: thread per (c,t), 32 independent LDGs -------
__global__ void __launch_bounds__(256)
reduce_kernel(float *__restrict__ out) {
    int blk = blockIdx.x;
    int bb = blk >> 7;
    int tp = blk & 127;
    int c = threadIdx.x & 127, th = threadIdx.x >> 7;
    int t = tp * 2 + th;
    const float *base = g_out2 + ((size_t)(bb * 32) * 256 + t) * 128 + c;
    float a0 = 0.f, a1 = 0.f, a2 = 0.f, a3 = 0.f;
#pragma unroll
    for (int n = 0; n < 32; n += 4) {
        a0 += base[(size_t)(n + 0) * 32768];
        a1 += base[(size_t)(n + 1) * 32768];
        a2 += base[(size_t)(n + 2) * 32768];
        a3 += base[(size_t)(n + 3) * 32768];
    }
    out[((bb * 128 + c) << 8) + t] = (a0 + a1) + (a2 + a3);
}

extern "C" void kernel_launch(void* const* d_in, const int* in_sizes, int n_in,
                              void* d_out, int out_size) {
    const float *x     = (const float *)d_in[0];
    const float *mlp_w = (const float *)d_in[1];
    const float *mlp_b = (const float *)d_in[2];
    const float *wq = (const float *)d_in[3],  *bq = (const float *)d_in[4];
    const float *wk = (const float *)d_in[5],  *bk = (const float *)d_in[6];
    const float *wv = (const float *)d_in[7],  *bv = (const float *)d_in[8];
    const float *wo = (const float *)d_in[9],  *bo = (const float *)d_in[10];
    const float *w1 = (const float *)d_in[11], *b1 = (const float *)d_in[12];
    const float *w2 = (const float *)d_in[13], *b2 = (const float *)d_in[14];
    const float *ln1g = (const float *)d_in[15], *ln1b = (const float *)d_in[16];
    const float *ln2g = (const float *)d_in[17], *ln2b = (const float *)d_in[18];
    float *out = (float *)d_out;

    setup_a<<<185, 256>>>(mlp_w, mlp_b, wq, bq, wk, bk, wv, bv, w2, w1);
    setup_b<<<17, 256>>>(wo, bo);
    setup_c<<<15, 256>>>(mlp_w, mlp_b, ln1g, ln1b);
    setup_d<<<64, 256>>>(b1);
    attn_kernel<<<1024, 256>>>(x);
    ffn_kernel<<<TOK / 32, 256>>>(x, b2, ln2g, ln2b);
    reduce_kernel<<<512, 256>>>(out);
}

// round 17
// speedup vs baseline: 1.1091x; 1.1091x over previous
#include <cuda_runtime.h>
#include <cuda_bf16.h>
#include <math.h>
#include <cstdint>

// InformerLayer: b=4,N=32,T=256 -> B=128 seqs, L=256, C=128, H=8, E=16, DFF=512, u=k=18
#define TOK 32768
#define UK  18

__device__ float g_Aq[128], g_Bq[128], g_Ak[128], g_Bk[128], g_Av[128], g_Bv[128];
__device__ float g_c1[8], g_c2[8], g_c3[8], g_c4[8];
__device__ float g_Po[8 * 128], g_Co[128];
__device__ int   g_idx[256 * UK];
__device__ float g_zm[10];
__device__ float g_G[100];
__device__ float g_V[12 * 128];
__device__ float g_u[TOK * 12];
__device__ unsigned g_ubf[TOK * 8];
__device__ float g_out2[TOK * 128];
__device__ float g_w1c[512 * 128];           // L2-warm copy of w1
__device__ uint2 g_w1f2[64 * 32];            // W1' B-frags: [ntile][lane]
__device__ unsigned g_w2f[16 * 16 * 32 * 4]; // w2 B-frags: [nb][g][lane][4]

static __device__ __forceinline__ unsigned packbf(float a, float b) {
    __nv_bfloat162 t = __floats2bfloat162_rn(a, b);
    return *reinterpret_cast<unsigned *>(&t);
}

__device__ __forceinline__ void mma16816(float &d0, float &d1, float &d2, float &d3,
                                         unsigned a0, unsigned a1, unsigned a2, unsigned a3,
                                         unsigned b0, unsigned b1) {
    asm volatile("mma.sync.aligned.m16n8k16.row.col.f32.bf16.bf16.f32 "
                 "{%0,%1,%2,%3},{%4,%5,%6,%7},{%8,%9},{%0,%1,%2,%3};"
                 : "+f"(d0), "+f"(d1), "+f"(d2), "+f"(d3)
                 : "r"(a0), "r"(a1), "r"(a2), "r"(a3), "r"(b0), "r"(b1));
}

#define LDMX4(r, addr) \
    asm volatile("ldmatrix.sync.aligned.m8n8.x4.shared.b16 {%0,%1,%2,%3}, [%4];" \
                 : "=r"((r)[0]), "=r"((r)[1]), "=r"((r)[2]), "=r"((r)[3]) : "r"(addr))

static __device__ __forceinline__ uint32_t smem_u32(const void *p) {
    uint32_t a;
    asm("{ .reg .u64 t; cvta.to.shared.u64 t, %1; cvt.u32.u64 %0, t; }" : "=r"(a) : "l"(p));
    return a;
}

// monotone int key: unsigned compare == float compare (no NaNs in inputs)
static __device__ __forceinline__ unsigned fkey(float f) {
    int m = __float_as_int(f);
    return (unsigned)m ^ ((unsigned)(m >> 31) | 0x80000000u);
}

// ------------------------------- Threefry ---------------------------------
__device__ __forceinline__ void tf_r(unsigned &x0, unsigned &x1, int r) {
    x0 += x1; x1 = (x1 << r) | (x1 >> (32 - r)); x1 ^= x0;
}
__device__ void threefry2x32(unsigned k0, unsigned k1, unsigned c0, unsigned c1,
                             unsigned &o0, unsigned &o1) {
    unsigned ks2 = k0 ^ k1 ^ 0x1BD11BDAu;
    unsigned x0 = c0 + k0, x1 = c1 + k1;
    tf_r(x0,x1,13); tf_r(x0,x1,15); tf_r(x0,x1,26); tf_r(x0,x1,6);
    x0 += k1;  x1 += ks2 + 1u;
    tf_r(x0,x1,17); tf_r(x0,x1,29); tf_r(x0,x1,16); tf_r(x0,x1,24);
    x0 += ks2; x1 += k0 + 2u;
    tf_r(x0,x1,13); tf_r(x0,x1,15); tf_r(x0,x1,26); tf_r(x0,x1,6);
    x0 += k0;  x1 += k1 + 3u;
    tf_r(x0,x1,17); tf_r(x0,x1,29); tf_r(x0,x1,16); tf_r(x0,x1,24);
    x0 += k1;  x1 += ks2 + 4u;
    tf_r(x0,x1,13); tf_r(x0,x1,15); tf_r(x0,x1,26); tf_r(x0,x1,6);
    x0 += ks2; x1 += k0 + 5u;
    o0 = x0; o1 = x1;
}

// ---- setup_a: Aq..Bv + threefry idx + w2 frags + w1 L2-warm copy ----------
__global__ void __launch_bounds__(256)
setup_a(const float *__restrict__ mlp_w, const float *__restrict__ mlp_b,
        const float *__restrict__ wq, const float *__restrict__ bq,
        const float *__restrict__ wk, const float *__restrict__ bk,
        const float *__restrict__ wv, const float *__restrict__ bv,
        const float *__restrict__ w2, const float *__restrict__ w1) {
    int b = blockIdx.x, tid = threadIdx.x, lane = tid & 31, wid = tid >> 5;
    if (b < 16) {
        int c = b * 8 + wid;
        float aq = 0.f, bq2 = 0.f, ak = 0.f, bk2 = 0.f, av = 0.f, bv2 = 0.f;
#pragma unroll
        for (int m = 0; m < 4; ++m) {
            int j = lane + 32 * m;
            float mw = mlp_w[j], mb = mlp_b[j];
            float q = wq[c * 128 + j], k = wk[c * 128 + j], v = wv[c * 128 + j];
            aq = fmaf(mw, q, aq); bq2 = fmaf(mb, q, bq2);
            ak = fmaf(mw, k, ak); bk2 = fmaf(mb, k, bk2);
            av = fmaf(mw, v, av); bv2 = fmaf(mb, v, bv2);
        }
#pragma unroll
        for (int o = 16; o > 0; o >>= 1) {
            aq  += __shfl_xor_sync(0xffffffffu, aq, o);
            bq2 += __shfl_xor_sync(0xffffffffu, bq2, o);
            ak  += __shfl_xor_sync(0xffffffffu, ak, o);
            bk2 += __shfl_xor_sync(0xffffffffu, bk2, o);
            av  += __shfl_xor_sync(0xffffffffu, av, o);
            bv2 += __shfl_xor_sync(0xffffffffu, bv2, o);
        }
        if (lane == 0) {
            g_Aq[c] = aq; g_Bq[c] = bq2 + bq[c];
            g_Ak[c] = ak; g_Bk[c] = bk2 + bk[c];
            g_Av[c] = av; g_Bv[c] = bv2 + bv[c];
        }
    } else if (b < 25) {
        int i = (b - 16) * 256 + tid;
        unsigned a0, a1, b0, b1;
        threefry2x32(0u, 42u, 0u, 2u, a0, a1);
        threefry2x32(0u, 42u, 1u, 3u, b0, b1);
        unsigned y0, y1;
        threefry2x32(a1, b1, (unsigned)i, (unsigned)(2304 + i), y0, y1);
        g_idx[i]        = (int)(y0 & 255u);
        g_idx[2304 + i] = (int)(y1 & 255u);
    } else if (b < 153) {
        int j2 = (b - 25) * 256 + tid;
        int jj = j2 & 3, u4 = j2 >> 2;
        int ln = u4 & 31, g = (u4 >> 5) & 15, nb = u4 >> 9;
        int n = nb * 8 + (ln >> 2);
        int kp = g * 16 + (ln & 3) + jj * 4;
        g_w2f[j2] = packbf(w2[n * 512 + 2 * kp], w2[n * 512 + 2 * kp + 1]);
    } else {
        int j = (b - 153) * 256 + tid;
        const float4 *src = (const float4 *)w1;
        float4 *dst = (float4 *)g_w1c;
        dst[j] = src[j];
        dst[j + 8192] = src[j + 8192];
    }
}

// ---- setup_b: Co + Po (warp/c) + c1..c4 ------------------------------------
__global__ void __launch_bounds__(256)
setup_b(const float *__restrict__ wo, const float *__restrict__ bo) {
    int b = blockIdx.x, tid = threadIdx.x, lane = tid & 31, wid = tid >> 5;
    if (b < 16) {
        int c = b * 8 + wid;
        float co = 0.f, pv[4];
#pragma unroll
        for (int m = 0; m < 4; ++m) {
            int j = lane + 32 * m;
            float w = wo[c * 128 + j];
            co = fmaf(g_Bv[j], w, co);
            pv[m] = g_Av[j] * w;
        }
#pragma unroll
        for (int o = 16; o > 0; o >>= 1) co += __shfl_xor_sync(0xffffffffu, co, o);
#pragma unroll
        for (int o = 8; o > 0; o >>= 1)
#pragma unroll
            for (int m = 0; m < 4; ++m) pv[m] += __shfl_xor_sync(0xffffffffu, pv[m], o);
        if ((lane & 15) == 0) {
            int hb = lane >> 4;
#pragma unroll
            for (int m = 0; m < 4; ++m) g_Po[(hb + 2 * m) * 128 + c] = pv[m];
        }
        if (lane == 0) g_Co[c] = co + bo[c];
    } else {
        if (tid < 8) {
            int h = tid;
            float c1 = 0.f, c2 = 0.f, c3 = 0.f, c4 = 0.f;
            for (int e = 0; e < 16; ++e) {
                int i = h * 16 + e;
                c1 += g_Aq[i] * g_Ak[i];
                c2 += g_Aq[i] * g_Bk[i];
                c3 += g_Bq[i] * g_Ak[i];
                c4 += g_Bq[i] * g_Bk[i];
            }
            g_c1[h] = c1; g_c2[h] = c2; g_c3[h] = c3; g_c4[h] = c4;
        }
    }
}

// ---- mid_kernel: blocks 0..127 attn(+LN1 u); 128..191 W1' frags; 192 V+G/zm
__global__ void __launch_bounds__(256)
mid_kernel(const float *__restrict__ x,
           const float *__restrict__ mlp_w, const float *__restrict__ mlp_b,
           const float *__restrict__ ln1g, const float *__restrict__ ln1b,
           const float *__restrict__ b1) {
    int b = blockIdx.x, tid = threadIdx.x, lane = tid & 31, wid = tid >> 5;

    if (b >= 128) {
        // ---------- setup branch: V in smem; W1' frags or g_V+G/zm ----------
        __shared__ __align__(16) float Vs[12 * 128];
        __shared__ __align__(16) float zbs[10 * 128];
        __shared__ __align__(16) float sfr[8][12];
        if (tid < 128) {
            int c = tid;
            float K = mlp_b[c] + g_Co[c];
            float g = ln1g[c];
            float mw = mlp_w[c];
            Vs[0 * 128 + c] = mw * g;
#pragma unroll
            for (int h = 0; h < 8; ++h) {
                float po = g_Po[h * 128 + c];
                Vs[(1 + h) * 128 + c] = po * g;
                zbs[(1 + h) * 128 + c] = po;
            }
            Vs[9 * 128 + c]  = K * g;
            Vs[10 * 128 + c] = g;
            Vs[11 * 128 + c] = ln1b[c];
            zbs[0 * 128 + c] = mw;
            zbs[9 * 128 + c] = K;
            if (b == 192) {
#pragma unroll
                for (int k = 0; k < 12; ++k) g_V[k * 128 + c] = Vs[k * 128 + c];
            }
        }
        __syncthreads();

        if (b < 192) {
            int n = (b - 128) * 8 + wid;
            float4 wv = *(const float4 *)(g_w1c + n * 128 + lane * 4);
            float p[12];
#pragma unroll
            for (int k = 0; k < 12; ++k) {
                float4 v = *(const float4 *)(Vs + k * 128 + lane * 4);
                p[k] = wv.x * v.x + wv.y * v.y + wv.z * v.z + wv.w * v.w;
            }
#pragma unroll
            for (int o = 16; o > 0; o >>= 1)
#pragma unroll
                for (int k = 0; k < 12; ++k) p[k] += __shfl_xor_sync(0xffffffffu, p[k], o);
            if (lane == 0) {
#pragma unroll
                for (int k = 0; k < 11; ++k) sfr[wid][k] = p[k];
                sfr[wid][11] = p[11] + b1[n];
            }
            __syncthreads();
            if (wid == 0) {
                int nr = lane >> 2, q = lane & 3;
                float d0 = sfr[nr][2 * q], d1 = sfr[nr][2 * q + 1];
                float d2 = (2 * q + 8 < 12) ? sfr[nr][2 * q + 8] : 0.f;
                float d3 = (2 * q + 9 < 12) ? sfr[nr][2 * q + 9] : 0.f;
                g_w1f2[(b - 128) * 32 + lane] = make_uint2(packbf(d0, d1), packbf(d2, d3));
            }
        } else {
            for (int task = wid; task < 110; task += 8) {
                if (task < 100) {
                    int i = task / 10, j = task % 10;
                    float s = 0.f;
#pragma unroll
                    for (int m = 0; m < 4; ++m) {
                        int c = lane + 32 * m;
                        s = fmaf(zbs[i * 128 + c], zbs[j * 128 + c], s);
                    }
#pragma unroll
                    for (int o = 16; o > 0; o >>= 1) s += __shfl_xor_sync(0xffffffffu, s, o);
                    if (lane == 0) g_G[task] = s * (1.0f / 128.0f);
                } else {
                    int i = task - 100;
                    float s = 0.f;
#pragma unroll
                    for (int m = 0; m < 4; ++m) s += zbs[i * 128 + lane + 32 * m];
#pragma unroll
                    for (int o = 16; o > 0; o >>= 1) s += __shfl_xor_sync(0xffffffffu, s, o);
                    if (lane == 0) g_zm[i] = s * (1.0f / 128.0f);
                }
            }
        }
        return;
    }

    // ---------------- attn branch (R12 per-seq version) --------------------
    __shared__ __align__(16) float xs[256];
    __shared__ __align__(16) float al[256 * 8];
    __shared__ __align__(16) int   midx[8][UK];
    __shared__ __align__(16) float zm[12], Gs[100];
    __shared__ __align__(16) float pmx[256], pmn[256], psm[256];
    int h = wid;
    int seq = b;
    xs[tid] = x[seq * 256 + tid];
    __syncthreads();

    {
        float pm = -3.4e38f, pn = 3.4e38f, ps = 0.f;
        const int *ip = g_idx + tid * UK;
#pragma unroll
        for (int j = 0; j < UK; ++j) {
            float v = xs[ip[j]];
            pm = fmaxf(pm, v); pn = fminf(pn, v); ps += v;
        }
        pmx[tid] = pm; pmn[tid] = pn; psm[tid] = ps;
    }

    float s = 0.f, xmax = -3.4e38f, xmin = 3.4e38f;
#pragma unroll
    for (int k = 0; k < 8; ++k) {
        float v = xs[lane + 32 * k];
        s += v; xmax = fmaxf(xmax, v); xmin = fminf(xmin, v);
    }
#pragma unroll
    for (int o = 16; o > 0; o >>= 1) {
        s += __shfl_xor_sync(0xffffffffu, s, o);
        xmax = fmaxf(xmax, __shfl_xor_sync(0xffffffffu, xmax, o));
        xmin = fminf(xmin, __shfl_xor_sync(0xffffffffu, xmin, o));
    }
    float xbar = s * (1.0f / 256.0f);
    __syncthreads();

    float c1 = g_c1[h], c2 = g_c2[h], c3 = g_c3[h], c4 = g_c4[h];
    unsigned Mkey[8];
#pragma unroll
    for (int k = 0; k < 8; ++k) {
        int t = lane + 32 * k;
        float xl = xs[t];
        float A = fmaf(c1, xl, c3), Bc = fmaf(c2, xl, c4);
        float mx = (A >= 0.f ? A * pmx[t] : A * pmn[t]) + Bc;
        float sm = fmaf(A, psm[t], (float)UK * Bc);
        Mkey[k] = fkey(mx - sm * (1.0f / 256.0f));
        al[t * 8 + h] = xbar;
    }

    for (int it = 0; it < UK; ++it) {
        unsigned bkey = 0u; int bi = 256;
#pragma unroll
        for (int k = 0; k < 8; ++k) {
            if (Mkey[k] > bkey) { bkey = Mkey[k]; bi = lane + 32 * k; }
        }
        unsigned mkey = __reduce_max_sync(0xffffffffu, bkey);
        unsigned cand = (bkey == mkey) ? (unsigned)bi : 0xFFFFu;
        unsigned mi = __reduce_min_sync(0xffffffffu, cand);
        int m = (int)mi;
#pragma unroll
        for (int k = 0; k < 8; ++k)
            if ((m >> 5) == k && (m & 31) == lane) Mkey[k] = 0u;
        if (lane == 0) midx[h][it] = m;
    }
    // load G/zm while warps wait (before the sync the softmax needs)
    if (tid < 100) Gs[tid] = g_G[tid];
    if (tid >= 100 && tid < 110) zm[tid - 100] = g_zm[tid - 100];
    __syncthreads();

#pragma unroll
    for (int i = 0; i < 9; ++i) {
        int pa = h + 16 * i, pb = pa + 8;
        int ha = pa / UK, ita = pa % UK;
        int hb = pb / UK, itb = pb % UK;
        int ma = midx[ha][ita], mb = midx[hb][itb];
        float Aa = 0.25f * fmaf(g_c1[ha], xs[ma], g_c3[ha]);
        float Ab = 0.25f * fmaf(g_c1[hb], xs[mb], g_c3[hb]);
        float rma = (Aa >= 0.f) ? Aa * xmax : Aa * xmin;
        float rmb = (Ab >= 0.f) ? Ab * xmax : Ab * xmin;
        float Za = 0.f, Sa = 0.f, Zb = 0.f, Sb = 0.f;
#pragma unroll
        for (int k = 0; k < 8; ++k) {
            float xv = xs[lane + 32 * k];
            float ea = __expf(fmaf(Aa, xv, -rma));
            float eb = __expf(fmaf(Ab, xv, -rmb));
            Za += ea; Sa += ea * xv;
            Zb += eb; Sb += eb * xv;
        }
#pragma unroll
        for (int o = 16; o > 0; o >>= 1) {
            Za += __shfl_xor_sync(0xffffffffu, Za, o);
            Sa += __shfl_xor_sync(0xffffffffu, Sa, o);
            Zb += __shfl_xor_sync(0xffffffffu, Zb, o);
            Sb += __shfl_xor_sync(0xffffffffu, Sb, o);
        }
        if (lane == 0) {
            al[ma * 8 + ha] = Sa / Za;
            al[mb * 8 + hb] = Sb / Zb;
        }
    }
    __syncthreads();

    float y[10];
    y[0] = xs[tid];
#pragma unroll
    for (int hh = 0; hh < 8; ++hh) y[1 + hh] = al[tid * 8 + hh];
    y[9] = 1.f;
    float mu = 0.f;
#pragma unroll
    for (int i = 0; i < 10; ++i) mu = fmaf(y[i], zm[i], mu);
    float q2 = 0.f;
#pragma unroll
    for (int i = 0; i < 10; ++i) {
        float acc = 0.f;
#pragma unroll
        for (int j = 0; j < 10; ++j) acc = fmaf(Gs[i * 10 + j], y[j], acc);
        q2 = fmaf(y[i], acc, q2);
    }
    float var = q2 - mu * mu;
    float r = rsqrtf(var + 1e-5f);
    float u[12];
#pragma unroll
    for (int i = 0; i < 9; ++i) u[i] = y[i] * r;
    u[9] = r; u[10] = -mu * r; u[11] = 1.f;

    size_t row = (size_t)seq * 256 + tid;
    float4 *up = (float4 *)(g_u + row * 12);
    up[0] = make_float4(u[0], u[1], u[2], u[3]);
    up[1] = make_float4(u[4], u[5], u[6], u[7]);
    up[2] = make_float4(u[8], u[9], u[10], u[11]);
    uint4 *ub = (uint4 *)(g_ubf + row * 8);
    ub[0] = make_uint4(packbf(u[0], u[1]), packbf(u[2], u[3]),
                       packbf(u[4], u[5]), packbf(u[6], u[7]));
    ub[1] = make_uint4(packbf(u[8], u[9]), packbf(u[10], u[11]), 0u, 0u);
}

// ---------- FFN + residual + LN2; 32 rows/block (R12 configuration) ---------
#define OFF_US (32 * 260)
#define OFF_VS (OFF_US + 32 * 12)
#define OFF_B2 (OFF_VS + 12 * 128)
#define OFF_LG (OFF_B2 + 128)
#define OFF_LB (OFF_LG + 128)
#define FFN_U32 (OFF_LB + 128)

__global__ void __launch_bounds__(256)
ffn_kernel(const float *__restrict__ b2,
           const float *__restrict__ ln2g, const float *__restrict__ ln2b) {
    __shared__ __align__(16) unsigned ts[FFN_U32];
    float *us  = (float *)(ts + OFF_US);
    float *Vs  = (float *)(ts + OFF_VS);
    float *b2s = (float *)(ts + OFF_B2);
    float *lgs = (float *)(ts + OFF_LG);
    float *lbs = (float *)(ts + OFF_LB);
    int tid = threadIdx.x;
    int wid = tid >> 5, lane = tid & 31;
    int row0 = blockIdx.x * 32;
    int r = lane >> 2, q = lane & 3;
    int ms = wid >> 2, nq = wid & 3;

    for (int i = tid; i < 32 * 12; i += 256) us[i] = g_u[(size_t)row0 * 12 + i];
    for (int i = tid; i < 12 * 128; i += 256) Vs[i] = g_V[i];
    if (tid < 128) { b2s[tid] = b2[tid]; lgs[tid] = ln2g[tid]; lbs[tid] = ln2b[tid]; }

    // GEMM1: U[32,16] @ W1'^T -> relu -> ts bf16 [32][512]
    {
        const unsigned *U = g_ubf + (size_t)(row0 + ms * 16) * 8;
        unsigned a0 = U[r * 8 + q];
        unsigned a1 = U[(r + 8) * 8 + q];
        unsigned a2 = U[r * 8 + q + 4];
        unsigned a3 = U[(r + 8) * 8 + q + 4];
#pragma unroll 4
        for (int t = 0; t < 16; ++t) {
            int nb = nq * 16 + t;
            uint2 B = g_w1f2[nb * 32 + lane];
            float d0 = 0.f, d1 = 0.f, d2 = 0.f, d3 = 0.f;
            mma16816(d0, d1, d2, d3, a0, a1, a2, a3, B.x, B.y);
            d0 = fmaxf(d0, 0.f); d1 = fmaxf(d1, 0.f);
            d2 = fmaxf(d2, 0.f); d3 = fmaxf(d3, 0.f);
            ts[(ms * 16 + r) * 260 + nb * 4 + q]     = packbf(d0, d1);
            ts[(ms * 16 + r + 8) * 260 + nb * 4 + q] = packbf(d2, d3);
        }
    }
    __syncthreads();

    // GEMM2: T[32,512] @ w2^T
    float d[4][4];
#pragma unroll
    for (int t = 0; t < 4; ++t) { d[t][0]=0.f; d[t][1]=0.f; d[t][2]=0.f; d[t][3]=0.f; }
    {
        uint32_t lmbase = smem_u32(ts)
            + (uint32_t)((ms * 16 + ((lane >> 3) & 1) * 8 + (lane & 7)) * 1040)
            + (uint32_t)(((lane >> 4) & 1) * 16);
        const uint4 *W2 = (const uint4 *)g_w2f;
#pragma unroll 2
        for (int g = 0; g < 16; ++g) {
            unsigned a0v[4], a1v[4];
            LDMX4(a0v, lmbase + 64 * g);
            LDMX4(a1v, lmbase + 64 * g + 32);
#pragma unroll
            for (int t = 0; t < 4; ++t) {
                uint4 B = W2[(((nq * 4 + t) * 16) + g) * 32 + lane];
                mma16816(d[t][0], d[t][1], d[t][2], d[t][3],
                         a0v[0], a0v[1], a0v[2], a0v[3], B.x, B.y);
                mma16816(d[t][0], d[t][1], d[t][2], d[t][3],
                         a1v[0], a1v[1], a1v[2], a1v[3], B.z, B.w);
            }
        }
    }
    __syncthreads();

    // ys = y + b2 + residual (x1 = u@V fp32)
    float *ys = (float *)ts;
    {
        int rr = ms * 16 + r;
#pragma unroll
        for (int t = 0; t < 4; ++t) {
            int c0 = nq * 32 + t * 8 + q * 2;
            float x00 = 0.f, x01 = 0.f, x10 = 0.f, x11 = 0.f;
#pragma unroll
            for (int k = 0; k < 12; ++k) {
                float v0 = Vs[k * 128 + c0], v1 = Vs[k * 128 + c0 + 1];
                float uu0 = us[rr * 12 + k], uu1 = us[(rr + 8) * 12 + k];
                x00 = fmaf(uu0, v0, x00); x01 = fmaf(uu0, v1, x01);
                x10 = fmaf(uu1, v0, x10); x11 = fmaf(uu1, v1, x11);
            }
            float bbx = b2s[c0], bby = b2s[c0 + 1];
            ys[rr * 132 + c0]           = d[t][0] + bbx + x00;
            ys[rr * 132 + c0 + 1]       = d[t][1] + bby + x01;
            ys[(rr + 8) * 132 + c0]     = d[t][2] + bbx + x10;
            ys[(rr + 8) * 132 + c0 + 1] = d[t][3] + bby + x11;
        }
    }
    __syncthreads();

    // LN2: 8 warps x 4 rows
#pragma unroll
    for (int jj = 0; jj < 4; ++jj) {
        int rr = wid * 4 + jj;
        float z[4];
#pragma unroll
        for (int j = 0; j < 4; ++j) z[j] = ys[rr * 132 + lane + 32 * j];
        float s2 = z[0] + z[1] + z[2] + z[3];
#pragma unroll
        for (int o = 16; o > 0; o >>= 1) s2 += __shfl_xor_sync(0xffffffffu, s2, o);
        float mu = s2 * (1.0f / 128.0f);
        float v = 0.f;
#pragma unroll
        for (int j = 0; j < 4; ++j) { float dd = z[j] - mu; v += dd * dd; }
#pragma unroll
        for (int o = 16; o > 0; o >>= 1) v += __shfl_xor_sync(0xffffffffu, v, o);
        float rstd = rsqrtf(v * (1.0f / 128.0f) + 1e-5f);
#pragma unroll
        for (int j = 0; j < 4; ++j) {
            int c = lane + 32 * j;
            g_out2[(size_t)(row0 + rr) * 128 + c] = (z[j] - mu) * rstd * lgs[c] + lbs[c];
        }
    }
}

// ----- out[b,c,t] = sum_n out2: thread per (c,t), 32 independent LDGs -------
__global__ void __launch_bounds__(256)
reduce_kernel(float *__restrict__ out) {
    int blk = blockIdx.x;
    int bb = blk >> 7;
    int tp = blk & 127;
    int c = threadIdx.x & 127, th = threadIdx.x >> 7;
    int t = tp * 2 + th;
    const float *base = g_out2 + ((size_t)(bb * 32) * 256 + t) * 128 + c;
    float a0 = 0.f, a1 = 0.f, a2 = 0.f, a3 = 0.f;
#pragma unroll
    for (int n = 0; n < 32; n += 4) {
        a0 += base[(size_t)(n + 0) * 32768];
        a1 += base[(size_t)(n + 1) * 32768];
        a2 += base[(size_t)(n + 2) * 32768];
        a3 += base[(size_t)(n + 3) * 32768];
    }
    out[((bb * 128 + c) << 8) + t] = (a0 + a1) + (a2 + a3);
}

extern "C" void kernel_launch(void* const* d_in, const int* in_sizes, int n_in,
                              void* d_out, int out_size) {
    const float *x     = (const float *)d_in[0];
    const float *mlp_w = (const float *)d_in[1];
    const float *mlp_b = (const float *)d_in[2];
    const float *wq = (const float *)d_in[3],  *bq = (const float *)d_in[4];
    const float *wk = (const float *)d_in[5],  *bk = (const float *)d_in[6];
    const float *wv = (const float *)d_in[7],  *bv = (const float *)d_in[8];
    const float *wo = (const float *)d_in[9],  *bo = (const float *)d_in[10];
    const float *w1 = (const float *)d_in[11], *b1 = (const float *)d_in[12];
    const float *w2 = (const float *)d_in[13], *b2 = (const float *)d_in[14];
    const float *ln1g = (const float *)d_in[15], *ln1b = (const float *)d_in[16];
    const float *ln2g = (const float *)d_in[17], *ln2b = (const float *)d_in[18];
    float *out = (float *)d_out;

    setup_a<<<185, 256>>>(mlp_w, mlp_b, wq, bq, wk, bk, wv, bv, w2, w1);
    setup_b<<<17, 256>>>(wo, bo);
    mid_kernel<<<193, 256>>>(x, mlp_w, mlp_b, ln1g, ln1b, b1);
    ffn_kernel<<<TOK / 32, 256>>>(b2, ln2g, ln2b);
    reduce_kernel<<<512, 256>>>(out);
}